// round 4
// baseline (speedup 1.0000x reference)
#include <cuda_runtime.h>
#include <cuda_fp16.h>
#include <cstdint>

#define NQ 4096
#define NK 8192
#define DIM 1024

// ---------------------------------------------------------------------------
// Scratch (device globals; no allocation in kernel_launch)
// ---------------------------------------------------------------------------
__device__ __half g_Qh[(size_t)NQ * DIM];     //  8 MB fp16 Q
__device__ __half g_Kh[(size_t)NK * DIM];     // 16 MB fp16 K (= V, [k][n])
__device__ __half g_R [(size_t)NQ * NK];      // 64 MB fp16 R = exp(cos)-1
__device__ float  g_qninv[NQ];
__device__ float  g_kninv[NK];
__device__ float  g_rsum[NQ];
__device__ float  g_colsum[DIM];
__device__ float  g_colpart[128][DIM];
__device__ float  g_rpart[NK / 256][NQ];      // per-n-tile row partials (GEMM1)

// ---------------------------------------------------------------------------
// PTX helpers (plain sm_103-compatible: mma.sync / ldmatrix / cp.async)
// ---------------------------------------------------------------------------
__device__ __forceinline__ uint32_t smem_u32(const void* p) {
    uint32_t a;
    asm("{ .reg .u64 t; cvta.to.shared.u64 t, %1; cvt.u32.u64 %0, t; }"
        : "=r"(a) : "l"(p));
    return a;
}
__device__ __forceinline__ void cp16(uint32_t dst, const void* src) {
    asm volatile("cp.async.cg.shared.global [%0], [%1], 16;" :: "r"(dst), "l"(src));
}
#define CP_COMMIT() asm volatile("cp.async.commit_group;" ::: "memory")
#define CP_WAIT(N)  asm volatile("cp.async.wait_group %0;" :: "n"(N) : "memory")

__device__ __forceinline__ void ldsm_x4(uint32_t (&r)[4], uint32_t addr) {
    asm volatile("ldmatrix.sync.aligned.m8n8.x4.shared.b16 {%0,%1,%2,%3}, [%4];"
        : "=r"(r[0]), "=r"(r[1]), "=r"(r[2]), "=r"(r[3]) : "r"(addr));
}
__device__ __forceinline__ void ldsm_x4_t(uint32_t (&r)[4], uint32_t addr) {
    asm volatile("ldmatrix.sync.aligned.m8n8.x4.trans.shared.b16 {%0,%1,%2,%3}, [%4];"
        : "=r"(r[0]), "=r"(r[1]), "=r"(r[2]), "=r"(r[3]) : "r"(addr));
}
__device__ __forceinline__ void mma16816(float (&d)[4], const uint32_t (&a)[4],
                                         uint32_t b0, uint32_t b1) {
    asm volatile("mma.sync.aligned.m16n8k16.row.col.f32.f16.f16.f32 "
        "{%0,%1,%2,%3}, {%4,%5,%6,%7}, {%8,%9}, {%0,%1,%2,%3};"
        : "+f"(d[0]), "+f"(d[1]), "+f"(d[2]), "+f"(d[3])
        : "r"(a[0]), "r"(a[1]), "r"(a[2]), "r"(a[3]), "r"(b0), "r"(b1));
}

// ---------------------------------------------------------------------------
// Aux kernels
// ---------------------------------------------------------------------------
__global__ void convert_norm_kernel(const float* __restrict__ X,
                                    __half* __restrict__ Xh,
                                    float* __restrict__ ninv) {
    int row  = blockIdx.x * 8 + (threadIdx.x >> 5);
    int lane = threadIdx.x & 31;
    const float4* xp = (const float4*)(X + (size_t)row * DIM);
    __half2* op = (__half2*)(Xh + (size_t)row * DIM);
    float s = 0.f;
#pragma unroll
    for (int i = 0; i < 8; i++) {
        float4 v = xp[lane + 32 * i];
        s += v.x * v.x + v.y * v.y + v.z * v.z + v.w * v.w;
        op[(lane + 32 * i) * 2]     = __floats2half2_rn(v.x, v.y);
        op[(lane + 32 * i) * 2 + 1] = __floats2half2_rn(v.z, v.w);
    }
#pragma unroll
    for (int o = 16; o > 0; o >>= 1) s += __shfl_xor_sync(0xffffffffu, s, o);
    if (lane == 0) ninv[row] = rsqrtf(s);
}

__global__ void colsum_part_kernel(const float* __restrict__ V) {
    int n = blockIdx.x * 256 + threadIdx.x;
    int kbase = blockIdx.y * 64;
    float s = 0.f;
#pragma unroll 8
    for (int k = 0; k < 64; k++) s += V[(size_t)(kbase + k) * DIM + n];
    g_colpart[blockIdx.y][n] = s;
}
__global__ void colsum_fin_kernel() {
    int n = blockIdx.x * 256 + threadIdx.x;
    float s = 0.f;
#pragma unroll
    for (int j = 0; j < 128; j++) s += g_colpart[j][n];
    g_colsum[n] = s;
}
__global__ void rowsum_fin_kernel() {
    int m = blockIdx.x * 256 + threadIdx.x;
    float s = (float)NK;
#pragma unroll
    for (int j = 0; j < NK / 256; j++) s += g_rpart[j][m];
    g_rsum[m] = s;
}

// ---------------------------------------------------------------------------
// HMMA fp16 GEMM, tile 128(M) x 256(N) x 32(K), 256 threads, 3-stage cp.async
//   MODE 0: A=Qh [m][k], B=Kh [n][k] (K-major, normal ldmatrix)
//           epilogue r = exp(acc*qninv*kninv)-1 -> g_R; row partials -> g_rpart
//   MODE 1: A=R [m][k],  B=Kh(=V) [k][n] (N-major, ldmatrix.trans)
//           epilogue (acc + colsum[n]) / rsum[m] -> Cout
// ---------------------------------------------------------------------------
#define BM 128
#define BN 256
#define BK 32
#define STAGES 3
#define APITCH_B 80                      // A row pitch bytes (40 halves)
#define A_BYTES  (BM * APITCH_B)         // 10240
#define BPITCH0_B 80                     // MODE0 B: [n][k] pitch bytes
#define BPITCH1_B 528                    // MODE1 B: [k][n] pitch bytes (264 halves)

template <int MODE>
__global__ __launch_bounds__(256, 1) void hgemm_kernel(
    const __half* __restrict__ A, const __half* __restrict__ B,
    int lda, int ldb, int kdim, float* __restrict__ Cout) {
    constexpr int B_BYTES = (MODE == 0) ? (BN * BPITCH0_B) : (BK * BPITCH1_B);
    constexpr int STAGE   = A_BYTES + B_BYTES;

    extern __shared__ char smem[];
    const uint32_t sbase = smem_u32(smem);
    const int t = threadIdx.x;
    const int m0 = blockIdx.y * BM, n0 = blockIdx.x * BN;
    const int lane = t & 31, w = t >> 5;
    const int wm = w >> 1, wn = w & 1;           // 4 x 2 warps; warp tile 32m x 128n
    const int lrow = lane & 15, lcol = (lane >> 4) * 16;

    auto load_stage = [&](int ci, int st) {
        uint32_t sa = sbase + st * STAGE;
        uint32_t sb = sa + A_BYTES;
        int k0 = ci * BK;
#pragma unroll
        for (int j = 0; j < 2; j++) {            // A: 128 rows x 4 x 16B
            int idx = t + 256 * j; int r = idx >> 2, c = idx & 3;
            cp16(sa + r * APITCH_B + c * 16, A + (size_t)(m0 + r) * lda + k0 + c * 8);
        }
        if (MODE == 0) {
#pragma unroll
            for (int j = 0; j < 4; j++) {        // B: 256 rows x 4 x 16B
                int idx = t + 256 * j; int r = idx >> 2, c = idx & 3;
                cp16(sb + r * BPITCH0_B + c * 16, B + (size_t)(n0 + r) * ldb + k0 + c * 8);
            }
        } else {
#pragma unroll
            for (int j = 0; j < 4; j++) {        // B: 32 k-rows x 32 x 16B
                int idx = t + 256 * j; int r = idx >> 5, c = idx & 31;
                cp16(sb + r * BPITCH1_B + c * 16, B + (size_t)(k0 + r) * ldb + n0 + c * 8);
            }
        }
    };

    float acc[2][16][4] = {};

    const int KT = kdim / BK;
    load_stage(0, 0); CP_COMMIT();
    load_stage(1, 1); CP_COMMIT();

    for (int i = 0; i < KT; i++) {
        CP_WAIT(1);
        __syncthreads();
        if (i + 2 < KT) load_stage(i + 2, (i + 2) % STAGES);
        CP_COMMIT();

        uint32_t sa = sbase + (i % STAGES) * STAGE;
        uint32_t sb = sa + A_BYTES;

#pragma unroll
        for (int kk = 0; kk < 2; kk++) {
            uint32_t a[2][4];
#pragma unroll
            for (int mi = 0; mi < 2; mi++)
                ldsm_x4(a[mi], sa + (wm * 32 + mi * 16 + lrow) * APITCH_B + kk * 32 + lcol);
#pragma unroll
            for (int ni = 0; ni < 8; ni++) {
                uint32_t bf[4];
                if (MODE == 0) {
                    ldsm_x4(bf, sb + (wn * 128 + ni * 16 + lrow) * BPITCH0_B + kk * 32 + lcol);
#pragma unroll
                    for (int mi = 0; mi < 2; mi++) {
                        mma16816(acc[mi][2 * ni],     a[mi], bf[0], bf[2]);
                        mma16816(acc[mi][2 * ni + 1], a[mi], bf[1], bf[3]);
                    }
                } else {
                    ldsm_x4_t(bf, sb + (kk * 16 + lrow) * BPITCH1_B
                                    + (wn * 128 + ni * 16 + ((lane >> 4) << 3)) * 2);
#pragma unroll
                    for (int mi = 0; mi < 2; mi++) {
                        mma16816(acc[mi][2 * ni],     a[mi], bf[0], bf[1]);
                        mma16816(acc[mi][2 * ni + 1], a[mi], bf[2], bf[3]);
                    }
                }
            }
        }
    }

    // ---- Epilogue ----
    const int g = lane >> 2, q = lane & 3;
    const int rbase = m0 + wm * 32;
    const int cbase = n0 + wn * 128;

    if (MODE == 0) {
        float* rp_s = (float*)(smem + STAGES * STAGE);   // [2][128]
        float rs[2][2] = {};
#pragma unroll
        for (int mi = 0; mi < 2; mi++) {
            int r0 = rbase + mi * 16 + g;
            float qi0 = g_qninv[r0], qi1 = g_qninv[r0 + 8];
            __half2* d0 = (__half2*)(g_R + (size_t)r0 * NK);
            __half2* d1 = (__half2*)(g_R + (size_t)(r0 + 8) * NK);
#pragma unroll
            for (int nj = 0; nj < 16; nj++) {
                int c = cbase + nj * 8 + q * 2;
                float kn0 = g_kninv[c], kn1 = g_kninv[c + 1];
                float e00 = __expf(acc[mi][nj][0] * qi0 * kn0) - 1.f;
                float e01 = __expf(acc[mi][nj][1] * qi0 * kn1) - 1.f;
                float e10 = __expf(acc[mi][nj][2] * qi1 * kn0) - 1.f;
                float e11 = __expf(acc[mi][nj][3] * qi1 * kn1) - 1.f;
                rs[mi][0] += e00 + e01;
                rs[mi][1] += e10 + e11;
                d0[c >> 1] = __floats2half2_rn(e00, e01);
                d1[c >> 1] = __floats2half2_rn(e10, e11);
            }
        }
        // quad-reduce (lanes sharing a row): xor 1, 2
#pragma unroll
        for (int mi = 0; mi < 2; mi++)
#pragma unroll
            for (int h = 0; h < 2; h++) {
                float v = rs[mi][h];
                v += __shfl_xor_sync(0xffffffffu, v, 1);
                v += __shfl_xor_sync(0xffffffffu, v, 2);
                rs[mi][h] = v;
            }
        if (q == 0) {
#pragma unroll
            for (int mi = 0; mi < 2; mi++)
#pragma unroll
                for (int h = 0; h < 2; h++)
                    rp_s[wn * 128 + wm * 32 + mi * 16 + h * 8 + g] = rs[mi][h];
        }
        __syncthreads();
        if (t < 128)
            g_rpart[blockIdx.x][m0 + t] = rp_s[t] + rp_s[128 + t];
    } else {
#pragma unroll
        for (int mi = 0; mi < 2; mi++) {
            int r0 = rbase + mi * 16 + g;
            float ri0 = 1.0f / g_rsum[r0], ri1 = 1.0f / g_rsum[r0 + 8];
            float* d0 = Cout + (size_t)r0 * DIM;
            float* d1 = Cout + (size_t)(r0 + 8) * DIM;
#pragma unroll
            for (int nj = 0; nj < 16; nj++) {
                int c = cbase + nj * 8 + q * 2;
                float cs0 = g_colsum[c], cs1 = g_colsum[c + 1];
                *(float2*)(d0 + c) = make_float2((acc[mi][nj][0] + cs0) * ri0,
                                                 (acc[mi][nj][1] + cs1) * ri0);
                *(float2*)(d1 + c) = make_float2((acc[mi][nj][2] + cs0) * ri1,
                                                 (acc[mi][nj][3] + cs1) * ri1);
            }
        }
    }
}

#define SMEM0 (STAGES * (A_BYTES + BN * BPITCH0_B) + 1024)   // 93184
#define SMEM1 (STAGES * (A_BYTES + BK * BPITCH1_B))          // 81408

// ---------------------------------------------------------------------------
// Launch
// ---------------------------------------------------------------------------
extern "C" void kernel_launch(void* const* d_in, const int* in_sizes, int n_in,
                              void* d_out, int out_size) {
    const float* Q = (const float*)d_in[0];   // [4096, 1024]
    const float* K = (const float*)d_in[1];   // [8192, 1024] (keys == values)
    float* out = (float*)d_out;               // [4096, 1024]
    (void)in_sizes; (void)n_in; (void)out_size;

    void *Qh, *Kh, *R, *qn, *kn;
    cudaGetSymbolAddress(&Qh, g_Qh);
    cudaGetSymbolAddress(&Kh, g_Kh);
    cudaGetSymbolAddress(&R,  g_R);
    cudaGetSymbolAddress(&qn, g_qninv);
    cudaGetSymbolAddress(&kn, g_kninv);

    cudaFuncSetAttribute(hgemm_kernel<0>, cudaFuncAttributeMaxDynamicSharedMemorySize, SMEM0);
    cudaFuncSetAttribute(hgemm_kernel<1>, cudaFuncAttributeMaxDynamicSharedMemorySize, SMEM1);

    convert_norm_kernel<<<NQ / 8, 256>>>(Q, (__half*)Qh, (float*)qn);
    convert_norm_kernel<<<NK / 8, 256>>>(K, (__half*)Kh, (float*)kn);
    colsum_part_kernel<<<dim3(DIM / 256, 128), 256>>>(K);
    colsum_fin_kernel<<<DIM / 256, 256>>>();

    // GEMM1: R = exp(cos(Q,K)) - 1   [4096 x 8192] (+ fused row partials)
    hgemm_kernel<0><<<dim3(NK / BN, NQ / BM), 256, SMEM0>>>(
        (const __half*)Qh, (const __half*)Kh, DIM, DIM, DIM, nullptr);

    rowsum_fin_kernel<<<NQ / 256, 256>>>();

    // GEMM2: out = (R . V + colsumV) / rsum   [4096 x 1024], V = Kh [k][n]
    hgemm_kernel<1><<<dim3(DIM / BN, NQ / BM), 256, SMEM1>>>(
        (const __half*)R, (const __half*)Kh, NK, DIM, NK, out);
}

// round 5
// speedup vs baseline: 1.0756x; 1.0756x over previous
#include <cuda_runtime.h>
#include <cuda_fp16.h>
#include <cstdint>

#define NQ 4096
#define NK 8192
#define DIM 1024

// ---------------------------------------------------------------------------
// Scratch (device globals; no allocation in kernel_launch)
// ---------------------------------------------------------------------------
__device__ __half g_Qh[(size_t)NQ * DIM];     //  8 MB fp16 Q
__device__ __half g_Kh[(size_t)NK * DIM];     // 16 MB fp16 K (K-major)
__device__ __half g_Vt[(size_t)DIM * NK];     // 16 MB fp16 V^T [n][k]
__device__ __half g_R [(size_t)NQ * NK];      // 64 MB fp16 R = exp(cos)-1
__device__ float  g_qninv[NQ];
__device__ float  g_kninv[NK];
__device__ float  g_rsum[NQ];
__device__ float  g_colsum[DIM];
__device__ float  g_colpart[128][DIM];
__device__ float  g_rpart[NK / 128][NQ];      // per-n-tile row partials (GEMM1)

// ---------------------------------------------------------------------------
// PTX helpers (plain sm_103-compatible: mma.sync / ldmatrix / cp.async)
// ---------------------------------------------------------------------------
__device__ __forceinline__ uint32_t smem_u32(const void* p) {
    uint32_t a;
    asm("{ .reg .u64 t; cvta.to.shared.u64 t, %1; cvt.u32.u64 %0, t; }"
        : "=r"(a) : "l"(p));
    return a;
}
__device__ __forceinline__ void cp16(uint32_t dst, const void* src) {
    asm volatile("cp.async.cg.shared.global [%0], [%1], 16;" :: "r"(dst), "l"(src));
}
#define CP_COMMIT() asm volatile("cp.async.commit_group;" ::: "memory")
#define CP_WAIT(N)  asm volatile("cp.async.wait_group %0;" :: "n"(N) : "memory")

__device__ __forceinline__ void ldsm_x4(uint32_t (&r)[4], uint32_t addr) {
    asm volatile("ldmatrix.sync.aligned.m8n8.x4.shared.b16 {%0,%1,%2,%3}, [%4];"
        : "=r"(r[0]), "=r"(r[1]), "=r"(r[2]), "=r"(r[3]) : "r"(addr));
}
__device__ __forceinline__ void mma16816(float (&d)[4], const uint32_t (&a)[4],
                                         uint32_t b0, uint32_t b1) {
    asm volatile("mma.sync.aligned.m16n8k16.row.col.f32.f16.f16.f32 "
        "{%0,%1,%2,%3}, {%4,%5,%6,%7}, {%8,%9}, {%0,%1,%2,%3};"
        : "+f"(d[0]), "+f"(d[1]), "+f"(d[2]), "+f"(d[3])
        : "r"(a[0]), "r"(a[1]), "r"(a[2]), "r"(a[3]), "r"(b0), "r"(b1));
}

// ---------------------------------------------------------------------------
// Aux kernels
// ---------------------------------------------------------------------------
__global__ void convert_norm_kernel(const float* __restrict__ X,
                                    __half* __restrict__ Xh,
                                    float* __restrict__ ninv) {
    int row  = blockIdx.x * 8 + (threadIdx.x >> 5);
    int lane = threadIdx.x & 31;
    const float4* xp = (const float4*)(X + (size_t)row * DIM);
    __half2* op = (__half2*)(Xh + (size_t)row * DIM);
    float s = 0.f;
#pragma unroll
    for (int i = 0; i < 8; i++) {
        float4 v = xp[lane + 32 * i];
        s += v.x * v.x + v.y * v.y + v.z * v.z + v.w * v.w;
        op[(lane + 32 * i) * 2]     = __floats2half2_rn(v.x, v.y);
        op[(lane + 32 * i) * 2 + 1] = __floats2half2_rn(v.z, v.w);
    }
#pragma unroll
    for (int o = 16; o > 0; o >>= 1) s += __shfl_xor_sync(0xffffffffu, s, o);
    if (lane == 0) ninv[row] = rsqrtf(s);
}

__global__ void transpose_v_kernel(const float* __restrict__ V) {
    __shared__ float tile[32][33];
    int n0 = blockIdx.x * 32, k0 = blockIdx.y * 32;
    int tx = threadIdx.x, ty = threadIdx.y;           // 32 x 8
#pragma unroll
    for (int i = 0; i < 4; i++)
        tile[ty + 8 * i][tx] = V[(size_t)(k0 + ty + 8 * i) * DIM + n0 + tx];
    __syncthreads();
#pragma unroll
    for (int i = 0; i < 4; i++)
        g_Vt[(size_t)(n0 + ty + 8 * i) * NK + k0 + tx] = __float2half(tile[tx][ty + 8 * i]);
}

__global__ void colsum_part_kernel(const float* __restrict__ V) {
    int n = blockIdx.x * 256 + threadIdx.x;
    int kbase = blockIdx.y * 64;
    float s = 0.f;
#pragma unroll 8
    for (int k = 0; k < 64; k++) s += V[(size_t)(kbase + k) * DIM + n];
    g_colpart[blockIdx.y][n] = s;
}
__global__ void colsum_fin_kernel() {
    int n = blockIdx.x * 256 + threadIdx.x;
    float s = 0.f;
#pragma unroll
    for (int j = 0; j < 128; j++) s += g_colpart[j][n];
    g_colsum[n] = s;
}
__global__ void rowsum_fin_kernel() {
    int m = blockIdx.x * 256 + threadIdx.x;
    float s = (float)NK;
#pragma unroll
    for (int j = 0; j < NK / 128; j++) s += g_rpart[j][m];
    g_rsum[m] = s;
}

// ---------------------------------------------------------------------------
// HMMA fp16 GEMM: 128x128x32 tile, 256 threads, 3-stage cp.async, 2 CTA/SM.
// Warp grid 4(m) x 2(n); warp tile 32m x 64n.
//   MODE 0: A=Qh[m][k], B=Kh[n][k]; epi r=exp(acc*qninv*kninv)-1 -> g_R,
//           fused per-CTA row sums -> g_rpart[blockIdx.x][m]
//   MODE 1: A=R[m][k],  B=Vt[n][k]; epi (acc + colsum[n]) / rsum[m] -> Cout
// ---------------------------------------------------------------------------
#define BM 128
#define BN 128
#define BK 32
#define STAGES 3
#define APITCH 40                              // halves per row (pad 32->40)
#define ST_A_BYTES (BM * APITCH * 2)           // 10240
#define ST_BYTES   (2 * ST_A_BYTES)            // 20480 (A + B)
#define SMEM_BYTES (STAGES * ST_BYTES + 1024)  // 62464 (incl. rp_s scratch)

template <int MODE>
__global__ __launch_bounds__(256, 2) void hgemm_kernel(
    const __half* __restrict__ A, const __half* __restrict__ B,
    int lda, int ldb, int kdim, float* __restrict__ Cout) {
    extern __shared__ char smem[];
    const uint32_t sbase = smem_u32(smem);
    const int t = threadIdx.x;
    const int m0 = blockIdx.y * BM, n0 = blockIdx.x * BN;
    const int lane = t & 31, w = t >> 5;
    const int wm = w >> 1, wn = w & 1;          // 4 x 2 warp grid; tile 32m x 64n
    const int lrow = lane & 15, lcol = (lane >> 4) * 16;

    auto load_stage = [&](int ci, int st) {
        uint32_t sa = sbase + st * ST_BYTES;
        uint32_t sb = sa + ST_A_BYTES;
        int k0 = ci * BK;
#pragma unroll
        for (int j = 0; j < 2; j++) {
            int idx = t + 256 * j;              // 0..511
            int r = idx >> 2, c = idx & 3;      // 128 rows x 4 chunks(16B)
            cp16(sa + r * (APITCH * 2) + c * 16,
                 A + (size_t)(m0 + r) * lda + k0 + c * 8);
            cp16(sb + r * (APITCH * 2) + c * 16,
                 B + (size_t)(n0 + r) * ldb + k0 + c * 8);
        }
    };

    float acc[2][8][4] = {};

    const int KT = kdim / BK;
    load_stage(0, 0); CP_COMMIT();
    load_stage(1, 1); CP_COMMIT();

    for (int i = 0; i < KT; i++) {
        CP_WAIT(1);
        __syncthreads();
        if (i + 2 < KT) load_stage(i + 2, (i + 2) % STAGES);
        CP_COMMIT();

        uint32_t sa = sbase + (i % STAGES) * ST_BYTES;
        uint32_t sb = sa + ST_A_BYTES;

#pragma unroll
        for (int kk = 0; kk < 2; kk++) {
            uint32_t a[2][4], bf[4][4];
#pragma unroll
            for (int mi = 0; mi < 2; mi++) {
                int row = wm * 32 + mi * 16 + lrow;
                ldsm_x4(a[mi], sa + row * (APITCH * 2) + kk * 32 + lcol);
            }
#pragma unroll
            for (int ni = 0; ni < 4; ni++) {
                int row = wn * 64 + ni * 16 + lrow;
                ldsm_x4(bf[ni], sb + row * (APITCH * 2) + kk * 32 + lcol);
            }
#pragma unroll
            for (int mi = 0; mi < 2; mi++)
#pragma unroll
                for (int ni = 0; ni < 4; ni++) {
                    mma16816(acc[mi][2 * ni],     a[mi], bf[ni][0], bf[ni][2]);
                    mma16816(acc[mi][2 * ni + 1], a[mi], bf[ni][1], bf[ni][3]);
                }
        }
    }

    // ---- Epilogue ----
    const int g = lane >> 2, q = lane & 3;
    const int rbase = m0 + wm * 32;
    const int cbase = n0 + wn * 64;

    if (MODE == 0) {
        float* rp_s = (float*)(smem + STAGES * ST_BYTES);   // [2][128]
        float rs[2][2] = {};
        float kn[8][2];
#pragma unroll
        for (int nj = 0; nj < 8; nj++) {
            int c = cbase + nj * 8 + q * 2;
            kn[nj][0] = g_kninv[c]; kn[nj][1] = g_kninv[c + 1];
        }
#pragma unroll
        for (int mi = 0; mi < 2; mi++) {
            int r0 = rbase + mi * 16 + g;
            float qi0 = g_qninv[r0], qi1 = g_qninv[r0 + 8];
            __half2* d0 = (__half2*)(g_R + (size_t)r0 * NK);
            __half2* d1 = (__half2*)(g_R + (size_t)(r0 + 8) * NK);
#pragma unroll
            for (int nj = 0; nj < 8; nj++) {
                int c = cbase + nj * 8 + q * 2;
                float e00 = __expf(acc[mi][nj][0] * qi0 * kn[nj][0]) - 1.f;
                float e01 = __expf(acc[mi][nj][1] * qi0 * kn[nj][1]) - 1.f;
                float e10 = __expf(acc[mi][nj][2] * qi1 * kn[nj][0]) - 1.f;
                float e11 = __expf(acc[mi][nj][3] * qi1 * kn[nj][1]) - 1.f;
                rs[mi][0] += e00 + e01;
                rs[mi][1] += e10 + e11;
                d0[c >> 1] = __floats2half2_rn(e00, e01);
                d1[c >> 1] = __floats2half2_rn(e10, e11);
            }
        }
        // reduce over the 4 q-lanes sharing each row
#pragma unroll
        for (int mi = 0; mi < 2; mi++)
#pragma unroll
            for (int h = 0; h < 2; h++) {
                float v = rs[mi][h];
                v += __shfl_xor_sync(0xffffffffu, v, 1);
                v += __shfl_xor_sync(0xffffffffu, v, 2);
                rs[mi][h] = v;
            }
        if (q == 0) {
#pragma unroll
            for (int mi = 0; mi < 2; mi++)
#pragma unroll
                for (int h = 0; h < 2; h++)
                    rp_s[wn * 128 + wm * 32 + mi * 16 + h * 8 + g] = rs[mi][h];
        }
        __syncthreads();
        if (t < 128)
            g_rpart[blockIdx.x][m0 + t] = rp_s[t] + rp_s[128 + t];
    } else {
#pragma unroll
        for (int mi = 0; mi < 2; mi++) {
            int r0 = rbase + mi * 16 + g;
            float ri0 = 1.0f / g_rsum[r0], ri1 = 1.0f / g_rsum[r0 + 8];
            float* d0 = Cout + (size_t)r0 * DIM;
            float* d1 = Cout + (size_t)(r0 + 8) * DIM;
#pragma unroll
            for (int nj = 0; nj < 8; nj++) {
                int c = cbase + nj * 8 + q * 2;
                float cs0 = g_colsum[c], cs1 = g_colsum[c + 1];
                *(float2*)(d0 + c) = make_float2((acc[mi][nj][0] + cs0) * ri0,
                                                 (acc[mi][nj][1] + cs1) * ri0);
                *(float2*)(d1 + c) = make_float2((acc[mi][nj][2] + cs0) * ri1,
                                                 (acc[mi][nj][3] + cs1) * ri1);
            }
        }
    }
}

// ---------------------------------------------------------------------------
// Launch
// ---------------------------------------------------------------------------
extern "C" void kernel_launch(void* const* d_in, const int* in_sizes, int n_in,
                              void* d_out, int out_size) {
    const float* Q = (const float*)d_in[0];   // [4096, 1024]
    const float* K = (const float*)d_in[1];   // [8192, 1024] (keys == values)
    float* out = (float*)d_out;               // [4096, 1024]
    (void)in_sizes; (void)n_in; (void)out_size;

    void *Qh, *Kh, *Vt, *R, *qn, *kn;
    cudaGetSymbolAddress(&Qh, g_Qh);
    cudaGetSymbolAddress(&Kh, g_Kh);
    cudaGetSymbolAddress(&Vt, g_Vt);
    cudaGetSymbolAddress(&R,  g_R);
    cudaGetSymbolAddress(&qn, g_qninv);
    cudaGetSymbolAddress(&kn, g_kninv);

    cudaFuncSetAttribute(hgemm_kernel<0>, cudaFuncAttributeMaxDynamicSharedMemorySize, SMEM_BYTES);
    cudaFuncSetAttribute(hgemm_kernel<1>, cudaFuncAttributeMaxDynamicSharedMemorySize, SMEM_BYTES);

    convert_norm_kernel<<<NQ / 8, 256>>>(Q, (__half*)Qh, (float*)qn);
    convert_norm_kernel<<<NK / 8, 256>>>(K, (__half*)Kh, (float*)kn);
    transpose_v_kernel<<<dim3(DIM / 32, NK / 32), dim3(32, 8)>>>(K);
    colsum_part_kernel<<<dim3(DIM / 256, 128), 256>>>(K);
    colsum_fin_kernel<<<DIM / 256, 256>>>();

    // GEMM1: R = exp(cos(Q,K)) - 1   [4096 x 8192] (+ fused row partials)
    hgemm_kernel<0><<<dim3(NK / BN, NQ / BM), 256, SMEM_BYTES>>>(
        (const __half*)Qh, (const __half*)Kh, DIM, DIM, DIM, nullptr);

    rowsum_fin_kernel<<<NQ / 256, 256>>>();

    // GEMM2: out = (R . V + colsumV) / rsum   [4096 x 1024]
    hgemm_kernel<1><<<dim3(DIM / BN, NQ / BM), 256, SMEM_BYTES>>>(
        (const __half*)R, (const __half*)Vt, NK, NK, NK, out);
}